// round 9
// baseline (speedup 1.0000x reference)
#include <cuda_runtime.h>
#include <cuda_fp16.h>

#define MAXN 100000
#define MAXE 1600000
#define HD   256
#define INF_ 128

// ---------------- scratch ----------------------------------------------------
__device__ __half g_fth[(size_t)MAXN * HD];   // 51.2 MB (L2-resident)
__device__ float  g_el[MAXN * 8];
__device__ float  g_er[MAXN * 8];
__device__ float  g_bmean[32];
__device__ int    g_deg[MAXN];
__device__ int    g_rowoff[MAXN + 1];
__device__ int    g_cursor[MAXN];
__device__ int    g_eids[MAXE];
__device__ int    g_bsum[1024];

// ---------------- init --------------------------------------------------------
__global__ void k_init(int n) {
    int i = blockIdx.x * blockDim.x + threadIdx.x;
    if (i < n) g_deg[i] = 0;
}

__global__ void k_bias(const float* __restrict__ bias) {
    int c = threadIdx.x;
    float s = 0.f;
#pragma unroll
    for (int h = 0; h < 8; h++) s += bias[h * 32 + c];
    g_bmean[c] = s * 0.125f;
}

// ---------------- GEMM + fused el/er epilogue, fp16 ft store -------------------
// block 1024 = 32 warps. warp w: cols [(w&15)*16, +16), node-half (w>>4)*64.
// lane l -> nodes half*64 + 2l, 2l+1. All smem reads conflict-free
// (fs: LDS.64 contiguous 256B/warp; Ws: warp-uniform broadcast).
__global__ __launch_bounds__(1024, 1)
void k_gemm(const float* __restrict__ feat, const float* __restrict__ W,
            const float* __restrict__ al, const float* __restrict__ ar, int n) {
    extern __shared__ float sm[];
    float* Ws  = sm;                         // 128 x 256          (128 KB)
    float* fs  = sm + 32768;                 // 128 k x 132 nodes  (67.6 KB)
    float* pel = sm + 32768 + 128 * 132;     // 128 x 17
    float* per = pel + 128 * 17;             // 128 x 17
    const int tid = threadIdx.x;
    const int n0  = blockIdx.x * 128;

    for (int i = tid; i < 8192; i += 1024)
        ((float4*)Ws)[i] = ((const float4*)W)[i];
    for (int i = tid; i < 4096; i += 1024) {
        int r = i >> 5, c4 = i & 31;
        float4 v = make_float4(0.f, 0.f, 0.f, 0.f);
        if (n0 + r < n) v = ((const float4*)feat)[(size_t)(n0 + r) * 32 + c4];
        fs[(4 * c4 + 0) * 132 + r] = v.x;
        fs[(4 * c4 + 1) * 132 + r] = v.y;
        fs[(4 * c4 + 2) * 132 + r] = v.z;
        fs[(4 * c4 + 3) * 132 + r] = v.w;
    }
    __syncthreads();

    const int w    = tid >> 5;
    const int lane = tid & 31;
    const int cw   = w & 15;          // col group
    const int nh   = w >> 4;          // node half (0/1)
    const int nb   = nh * 64 + 2 * lane;   // first of 2 nodes

    unsigned long long acc[16];       // [node i][col pair j]  i<2, j<8
#pragma unroll
    for (int i = 0; i < 16; i++) acc[i] = 0ULL;

    const float* fp = fs + nb;
    const float* wp = Ws + cw * 16;

#pragma unroll 2
    for (int k = 0; k < 128; k++) {
        float2 f = *(const float2*)(fp + k * 132);
        unsigned long long a0, a1;
        asm("mov.b64 %0, {%1, %1};" : "=l"(a0) : "r"(__float_as_uint(f.x)));
        asm("mov.b64 %0, {%1, %1};" : "=l"(a1) : "r"(__float_as_uint(f.y)));
        const ulonglong2* wv = (const ulonglong2*)(wp + (size_t)k * HD);
        {
            ulonglong2 u0 = wv[0], u1 = wv[1];
            unsigned long long wr[4] = {u0.x, u0.y, u1.x, u1.y};
#pragma unroll
            for (int j = 0; j < 4; j++) {
                asm("fma.rn.f32x2 %0, %1, %2, %0;" : "+l"(acc[j])     : "l"(a0), "l"(wr[j]));
                asm("fma.rn.f32x2 %0, %1, %2, %0;" : "+l"(acc[8 + j]) : "l"(a1), "l"(wr[j]));
            }
        }
        {
            ulonglong2 u2 = wv[2], u3 = wv[3];
            unsigned long long wr[4] = {u2.x, u2.y, u3.x, u3.y};
#pragma unroll
            for (int j = 0; j < 4; j++) {
                asm("fma.rn.f32x2 %0, %1, %2, %0;" : "+l"(acc[4 + j])  : "l"(a0), "l"(wr[j]));
                asm("fma.rn.f32x2 %0, %1, %2, %0;" : "+l"(acc[12 + j]) : "l"(a1), "l"(wr[j]));
            }
        }
    }

    float alv[16], arv[16];
#pragma unroll
    for (int j = 0; j < 16; j++) {
        alv[j] = __ldg(al + cw * 16 + j);
        arv[j] = __ldg(ar + cw * 16 + j);
    }

#pragma unroll
    for (int i = 0; i < 2; i++) {
        int node = nb + i;                  // tile-local
        float pl = 0.f, pr = 0.f;
        __half2 hv[8];
#pragma unroll
        for (int j = 0; j < 8; j++) {
            unsigned int lo, hi;
            asm("mov.b64 {%0, %1}, %2;" : "=r"(lo), "=r"(hi) : "l"(acc[i * 8 + j]));
            float flo = __uint_as_float(lo), fhi = __uint_as_float(hi);
            hv[j] = __floats2half2_rn(flo, fhi);
            pl += flo * alv[2 * j] + fhi * alv[2 * j + 1];
            pr += flo * arv[2 * j] + fhi * arv[2 * j + 1];
        }
        pel[node * 17 + cw] = pl;
        per[node * 17 + cw] = pr;
        if (n0 + node < n) {
            uint4* o = (uint4*)(g_fth + (size_t)(n0 + node) * HD + cw * 16);
            o[0] = *(uint4*)&hv[0];
            o[1] = *(uint4*)&hv[4];
        }
    }
    __syncthreads();

    if (tid < 1024) {
        int node = tid >> 3, h = tid & 7;
        if (n0 + node < n) {
            float el = 0.f, er = 0.f;
#pragma unroll
            for (int q = 0; q < 2; q++) {
                el += pel[node * 17 + 2 * h + q];
                er += per[node * 17 + 2 * h + q];
            }
            g_el[(n0 + node) * 8 + h] = el;
            g_er[(n0 + node) * 8 + h] = er;
        }
    }
}

// ---------------- CSR build ----------------------------------------------------
__global__ void k_hist(const int* __restrict__ dst, int e) {
    int i = blockIdx.x * blockDim.x + threadIdx.x;
    if (i < e) atomicAdd(&g_deg[dst[i]], 1);
}

__global__ void k_scan1(int n) {
    __shared__ int sm[1024];
    int i = blockIdx.x * 1024 + threadIdx.x;
    int v = (i < n) ? g_deg[i] : 0;
    sm[threadIdx.x] = v;
    __syncthreads();
    for (int off = 1; off < 1024; off <<= 1) {
        int t = (threadIdx.x >= off) ? sm[threadIdx.x - off] : 0;
        __syncthreads();
        sm[threadIdx.x] += t;
        __syncthreads();
    }
    if (i < n) g_rowoff[i] = sm[threadIdx.x] - v;
    if (threadIdx.x == 1023) g_bsum[blockIdx.x] = sm[1023];
}

__global__ void k_scan2(int nb) {
    if (threadIdx.x == 0 && blockIdx.x == 0) {
        int s = 0;
        for (int b = 0; b < nb; b++) { int t = g_bsum[b]; g_bsum[b] = s; s += t; }
    }
}

__global__ void k_scan3(int n, int e) {
    int i = blockIdx.x * 1024 + threadIdx.x;
    if (i < n) {
        int r = g_rowoff[i] + g_bsum[i >> 10];
        g_rowoff[i] = r;
        g_cursor[i] = r;
    }
    if (i == 0) g_rowoff[n] = e;
}

__global__ void k_scatter(const int* __restrict__ dst, int e) {
    int i = blockIdx.x * blockDim.x + threadIdx.x;
    if (i < e) {
        int p = atomicAdd(&g_cursor[dst[i]], 1);
        g_eids[p] = i;
    }
}

__device__ __forceinline__ float pick4(float a0, float a1, float a2, float a3, int i) {
    float x = (i & 1) ? a1 : a0;
    float y = (i & 1) ? a3 : a2;
    return (i & 2) ? y : x;
}
__device__ __forceinline__ float pick8(const float v0, const float v1, const float v2,
                                       const float v3, const float v4, const float v5,
                                       const float v6, const float v7, int i) {
    float a = pick4(v0, v1, v2, v3, i & 3);
    float b = pick4(v4, v5, v6, v7, i & 3);
    return (i & 4) ? b : a;
}

// ---- fused online-softmax + aggregate: warp/node, fp16 gather ----------------
__global__ __launch_bounds__(256)
void k_agg(const int* __restrict__ src, float* __restrict__ out_h,
           float* __restrict__ out_attn, int n) {
    __shared__ float s_w[8][32][8];
    const unsigned FULL = 0xffffffffu;
    const int wid  = threadIdx.x >> 5;
    const int lane = threadIdx.x & 31;
    const int node = blockIdx.x * 8 + wid;
    if (node >= n) return;
    const int h0 = lane >> 2;
    const int beg = g_rowoff[node], end = g_rowoff[node + 1];

    float4 er0 = *(const float4*)(g_er + (size_t)node * 8);
    float4 er1 = *(const float4*)(g_er + (size_t)node * 8 + 4);
    const float er[8] = {er0.x, er0.y, er0.z, er0.w, er1.x, er1.y, er1.z, er1.w};

    float m[8], s_[8], acc[8];
#pragma unroll
    for (int h = 0; h < 8; h++) { m[h] = -1e30f; s_[h] = 0.f; acc[h] = 0.f; }

    for (int base = beg; base < end; base += 32) {
        const int p = base + lane;
        const bool valid = p < end;
        int sr = 0;
        if (valid) sr = src[g_eids[p]];

        float v[8];
        if (valid) {
            float4 l0 = *(const float4*)(g_el + (size_t)sr * 8);
            float4 l1 = *(const float4*)(g_el + (size_t)sr * 8 + 4);
            float lv[8] = {l0.x, l0.y, l0.z, l0.w, l1.x, l1.y, l1.z, l1.w};
#pragma unroll
            for (int h = 0; h < 8; h++) {
                float t = lv[h] + er[h];
                v[h] = t > 0.f ? t : 0.2f * t;
            }
        } else {
#pragma unroll
            for (int h = 0; h < 8; h++) v[h] = -1e30f;
        }

        float bm[8];
#pragma unroll
        for (int h = 0; h < 8; h++) bm[h] = v[h];
#pragma unroll
        for (int off = 16; off; off >>= 1)
#pragma unroll
            for (int h = 0; h < 8; h++)
                bm[h] = fmaxf(bm[h], __shfl_xor_sync(FULL, bm[h], off));

        float sc[8];
#pragma unroll
        for (int h = 0; h < 8; h++) {
            float nm = fmaxf(m[h], bm[h]);
            sc[h] = __expf(m[h] - nm);
            s_[h] *= sc[h];
            m[h] = nm;
        }
        float scH = pick8(sc[0], sc[1], sc[2], sc[3], sc[4], sc[5], sc[6], sc[7], h0);
#pragma unroll
        for (int i = 0; i < 8; i++) acc[i] *= scH;

        float w[8];
#pragma unroll
        for (int h = 0; h < 8; h++) {
            w[h] = valid ? __expf(v[h] - m[h]) : 0.f;
            s_[h] += w[h];
        }
        *(float4*)&s_w[wid][lane][0] = make_float4(w[0], w[1], w[2], w[3]);
        *(float4*)&s_w[wid][lane][4] = make_float4(w[4], w[5], w[6], w[7]);
        __syncwarp();

        const int cnt = min(32, end - base);
        int j = 0;
        for (; j + 4 <= cnt; j += 4) {
            int s0 = __shfl_sync(FULL, sr, j);
            int s1 = __shfl_sync(FULL, sr, j + 1);
            int s2 = __shfl_sync(FULL, sr, j + 2);
            int s3 = __shfl_sync(FULL, sr, j + 3);
            uint4 u0 = ((const uint4*)(g_fth + (size_t)s0 * HD))[lane];
            uint4 u1 = ((const uint4*)(g_fth + (size_t)s1 * HD))[lane];
            uint4 u2 = ((const uint4*)(g_fth + (size_t)s2 * HD))[lane];
            uint4 u3 = ((const uint4*)(g_fth + (size_t)s3 * HD))[lane];
            float w0 = s_w[wid][j][h0], w1 = s_w[wid][j + 1][h0];
            float w2 = s_w[wid][j + 2][h0], w3 = s_w[wid][j + 3][h0];
#pragma unroll
            for (int t = 0; t < 4; t++) {
                float2 f0 = __half22float2(((const __half2*)&u0)[t]);
                float2 f1 = __half22float2(((const __half2*)&u1)[t]);
                float2 f2 = __half22float2(((const __half2*)&u2)[t]);
                float2 f3 = __half22float2(((const __half2*)&u3)[t]);
                acc[2 * t]     += w0 * f0.x + w1 * f1.x + w2 * f2.x + w3 * f3.x;
                acc[2 * t + 1] += w0 * f0.y + w1 * f1.y + w2 * f2.y + w3 * f3.y;
            }
        }
        for (; j < cnt; j++) {
            int s0 = __shfl_sync(FULL, sr, j);
            uint4 u0 = ((const uint4*)(g_fth + (size_t)s0 * HD))[lane];
            float w0 = s_w[wid][j][h0];
#pragma unroll
            for (int t = 0; t < 4; t++) {
                float2 f0 = __half22float2(((const __half2*)&u0)[t]);
                acc[2 * t]     += w0 * f0.x;
                acc[2 * t + 1] += w0 * f0.y;
            }
        }
        __syncwarp();
    }

#pragma unroll
    for (int off = 16; off; off >>= 1)
#pragma unroll
        for (int h = 0; h < 8; h++)
            s_[h] += __shfl_xor_sync(FULL, s_[h], off);
    float inv[8];
#pragma unroll
    for (int h = 0; h < 8; h++) inv[h] = (s_[h] > 0.f) ? 1.f / s_[h] : 0.f;

    // attn output (fp32 exact path)
    for (int p = beg + lane; p < end; p += 32) {
        int e = g_eids[p];
        int s = src[e];
        float4 l0 = *(const float4*)(g_el + (size_t)s * 8);
        float4 l1 = *(const float4*)(g_el + (size_t)s * 8 + 4);
        float lv[8] = {l0.x, l0.y, l0.z, l0.w, l1.x, l1.y, l1.z, l1.w};
        float a[8];
#pragma unroll
        for (int h = 0; h < 8; h++) {
            float t = lv[h] + er[h];
            t = t > 0.f ? t : 0.2f * t;
            a[h] = __expf(t - m[h]) * inv[h];
        }
        *(float4*)(out_attn + (size_t)e * 8)     = make_float4(a[0], a[1], a[2], a[3]);
        *(float4*)(out_attn + (size_t)e * 8 + 4) = make_float4(a[4], a[5], a[6], a[7]);
    }

    float invH = pick8(inv[0], inv[1], inv[2], inv[3], inv[4], inv[5], inv[6], inv[7], h0);
#pragma unroll
    for (int i = 0; i < 8; i++) acc[i] *= invH;
#pragma unroll
    for (int off = 4; off <= 16; off <<= 1)
#pragma unroll
        for (int i = 0; i < 8; i++)
            acc[i] += __shfl_xor_sync(FULL, acc[i], off);

    if (lane < 4) {
        float4 b0 = ((const float4*)g_bmean)[lane * 2];
        float4 b1 = ((const float4*)g_bmean)[lane * 2 + 1];
        float4* o = (float4*)(out_h + (size_t)node * 32 + lane * 8);
        o[0] = make_float4(acc[0] * 0.125f + b0.x, acc[1] * 0.125f + b0.y,
                           acc[2] * 0.125f + b0.z, acc[3] * 0.125f + b0.w);
        o[1] = make_float4(acc[4] * 0.125f + b1.x, acc[5] * 0.125f + b1.y,
                           acc[6] * 0.125f + b1.z, acc[7] * 0.125f + b1.w);
    }
}

// ---------------- launch --------------------------------------------------------
extern "C" void kernel_launch(void* const* d_in, const int* in_sizes, int n_in,
                              void* d_out, int out_size) {
    const float* feat = (const float*)d_in[0];
    const int*   src  = (const int*)d_in[1];
    const int*   dst  = (const int*)d_in[2];
    const float* W    = (const float*)d_in[3];
    const float* al   = (const float*)d_in[4];
    const float* ar   = (const float*)d_in[5];
    const float* bias = (const float*)d_in[6];

    int n = in_sizes[0] / INF_;
    int e = in_sizes[1];

    float* out      = (float*)d_out;
    float* out_h    = out;
    float* out_attn = out + (size_t)n * 32;

    const int SMEM = (32768 + 128 * 132 + 2 * 128 * 17) * 4;
    cudaFuncSetAttribute(k_gemm, cudaFuncAttributeMaxDynamicSharedMemorySize, SMEM);

    int nb = (n + 1023) / 1024;

    k_init<<<(n + 255) / 256, 256>>>(n);                          // 0
    k_hist<<<(e + 255) / 256, 256>>>(dst, e);                     // 1
    k_scan1<<<nb, 1024>>>(n);                                     // 2
    k_gemm<<<(n + 127) / 128, 1024, SMEM>>>(feat, W, al, ar, n);  // 3 <- profiled
    k_scan2<<<1, 32>>>(nb);                                       // 4
    k_scan3<<<nb, 1024>>>(n, e);                                  // 5
    k_scatter<<<(e + 255) / 256, 256>>>(dst, e);                  // 6
    k_bias<<<1, 32>>>(bias);                                      // 7
    k_agg<<<(n + 7) / 8, 256>>>(src, out_h, out_attn, n);         // 8
}

// round 10
// speedup vs baseline: 1.2027x; 1.2027x over previous
#include <cuda_runtime.h>
#include <cuda_fp16.h>

#define MAXN 100000
#define MAXE 1600000
#define HD   256
#define INF_ 128

// ---------------- scratch ----------------------------------------------------
__device__ __half g_fth[(size_t)MAXN * HD];   // 51.2 MB (L2-resident)
__device__ float  g_el[MAXN * 8];
__device__ float  g_er[MAXN * 8];
__device__ float  g_bmean[32];
__device__ int    g_deg[MAXN];
__device__ int    g_rowoff[MAXN + 1];
__device__ int    g_cursor[MAXN];
__device__ int    g_eids[MAXE];
__device__ int    g_bsum[1024];

// ---------------- init --------------------------------------------------------
__global__ void k_init(int n) {
    int i = blockIdx.x * blockDim.x + threadIdx.x;
    if (i < n) g_deg[i] = 0;
}

__global__ void k_bias(const float* __restrict__ bias) {
    int c = threadIdx.x;
    float s = 0.f;
#pragma unroll
    for (int h = 0; h < 8; h++) s += bias[h * 32 + c];
    g_bmean[c] = s * 0.125f;
}

__device__ __forceinline__ unsigned int f2tf32(float f) {
    unsigned int u;
    asm("cvt.rna.tf32.f32 %0, %1;" : "=r"(u) : "f"(f));
    return u;
}

// ---------------- TF32 tensor-core GEMM + fused el/er + fp16 ft ---------------
// block 512 = 16 warps, tile M=128 N=256 K=128, warp grid 4(M)x4(N), warp 32x64.
// A smem row-major [128][132]; W smem TRANSPOSED [n=256][k=132]. Both tf32.
__global__ __launch_bounds__(512, 1)
void k_gemm(const float* __restrict__ feat, const float* __restrict__ W,
            const float* __restrict__ al, const float* __restrict__ ar, int n) {
    extern __shared__ float sm[];
    unsigned int* As = (unsigned int*)sm;              // 128 x 132
    unsigned int* Bs = As + 128 * 132;                 // 256 x 132 (W^T)
    const int tid = threadIdx.x;
    const int n0  = blockIdx.x * 128;

    // fill A (feat tile), tf32-converted, zero-padded rows
    for (int i = tid; i < 4096; i += 512) {
        int r = i >> 5, c4 = i & 31;
        float4 v = make_float4(0.f, 0.f, 0.f, 0.f);
        if (n0 + r < n) v = ((const float4*)feat)[(size_t)(n0 + r) * 32 + c4];
        unsigned int* d = As + r * 132 + 4 * c4;
        d[0] = f2tf32(v.x); d[1] = f2tf32(v.y);
        d[2] = f2tf32(v.z); d[3] = f2tf32(v.w);
    }
    // fill W^T, tf32-converted
    for (int i = tid; i < 8192; i += 512) {
        int k = i >> 6, n4 = i & 63;
        float4 v = ((const float4*)W)[(size_t)k * 64 + n4];
        Bs[(4 * n4 + 0) * 132 + k] = f2tf32(v.x);
        Bs[(4 * n4 + 1) * 132 + k] = f2tf32(v.y);
        Bs[(4 * n4 + 2) * 132 + k] = f2tf32(v.z);
        Bs[(4 * n4 + 3) * 132 + k] = f2tf32(v.w);
    }
    __syncthreads();

    const unsigned FULL = 0xffffffffu;
    const int w    = tid >> 5;
    const int lane = tid & 31;
    const int mw   = w >> 2;          // M warp (0..3) -> rows mw*32..+31
    const int nw   = w & 3;           // N warp (0..3) -> cols nw*64..+63
    const int lr   = lane >> 2;       // 0..7
    const int lc   = lane & 3;        // 0..3

    float acc[2][8][4];
#pragma unroll
    for (int mt = 0; mt < 2; mt++)
#pragma unroll
        for (int nt = 0; nt < 8; nt++)
#pragma unroll
            for (int q = 0; q < 4; q++) acc[mt][nt][q] = 0.f;

#pragma unroll 1
    for (int kc = 0; kc < 16; kc++) {
        const int kb = kc * 8;
        unsigned int a[2][4];
#pragma unroll
        for (int mt = 0; mt < 2; mt++) {
            int r0 = mw * 32 + mt * 16 + lr;
            a[mt][0] = As[r0 * 132 + kb + lc];
            a[mt][1] = As[(r0 + 8) * 132 + kb + lc];
            a[mt][2] = As[r0 * 132 + kb + 4 + lc];
            a[mt][3] = As[(r0 + 8) * 132 + kb + 4 + lc];
        }
        unsigned int b[8][2];
#pragma unroll
        for (int nt = 0; nt < 8; nt++) {
            int c0 = nw * 64 + nt * 8 + lr;
            b[nt][0] = Bs[c0 * 132 + kb + lc];
            b[nt][1] = Bs[c0 * 132 + kb + 4 + lc];
        }
#pragma unroll
        for (int mt = 0; mt < 2; mt++)
#pragma unroll
            for (int nt = 0; nt < 8; nt++)
                asm volatile(
                    "mma.sync.aligned.m16n8k8.row.col.f32.tf32.tf32.f32 "
                    "{%0,%1,%2,%3}, {%4,%5,%6,%7}, {%8,%9}, {%0,%1,%2,%3};"
                    : "+f"(acc[mt][nt][0]), "+f"(acc[mt][nt][1]),
                      "+f"(acc[mt][nt][2]), "+f"(acc[mt][nt][3])
                    : "r"(a[mt][0]), "r"(a[mt][1]), "r"(a[mt][2]), "r"(a[mt][3]),
                      "r"(b[nt][0]), "r"(b[nt][1]));
    }

    // ---- epilogue: fp16 ft store + fused el/er (heads local to warp) ----
#pragma unroll
    for (int mt = 0; mt < 2; mt++) {
#pragma unroll
        for (int rh = 0; rh < 2; rh++) {
            int row  = mw * 32 + mt * 16 + rh * 8 + lr;
            int node = n0 + row;
            bool ok  = node < n;
            if (ok) {
                __half* fo = g_fth + (size_t)node * HD + nw * 64 + 2 * lc;
#pragma unroll
                for (int nt = 0; nt < 8; nt++) {
                    __half2 hv = __floats2half2_rn(acc[mt][nt][rh * 2],
                                                   acc[mt][nt][rh * 2 + 1]);
                    *(__half2*)(fo + nt * 8) = hv;
                }
            }
#pragma unroll
            for (int hh = 0; hh < 2; hh++) {
                int head = 2 * nw + hh;
                float pl = 0.f, pr = 0.f;
#pragma unroll
                for (int nt4 = 0; nt4 < 4; nt4++) {
                    int nt  = hh * 4 + nt4;
                    int cih = 8 * nt4 + 2 * lc;
                    float v0 = acc[mt][nt][rh * 2], v1 = acc[mt][nt][rh * 2 + 1];
                    pl += v0 * __ldg(al + head * 32 + cih) + v1 * __ldg(al + head * 32 + cih + 1);
                    pr += v0 * __ldg(ar + head * 32 + cih) + v1 * __ldg(ar + head * 32 + cih + 1);
                }
                pl += __shfl_xor_sync(FULL, pl, 1);
                pl += __shfl_xor_sync(FULL, pl, 2);
                pr += __shfl_xor_sync(FULL, pr, 1);
                pr += __shfl_xor_sync(FULL, pr, 2);
                if (lc == 0 && ok) {
                    g_el[node * 8 + head] = pl;
                    g_er[node * 8 + head] = pr;
                }
            }
        }
    }
}

// ---------------- CSR build ----------------------------------------------------
__global__ void k_hist(const int* __restrict__ dst, int e) {
    int i = blockIdx.x * blockDim.x + threadIdx.x;
    if (i < e) atomicAdd(&g_deg[dst[i]], 1);
}

__global__ void k_scan1(int n) {
    __shared__ int sm[1024];
    int i = blockIdx.x * 1024 + threadIdx.x;
    int v = (i < n) ? g_deg[i] : 0;
    sm[threadIdx.x] = v;
    __syncthreads();
    for (int off = 1; off < 1024; off <<= 1) {
        int t = (threadIdx.x >= off) ? sm[threadIdx.x - off] : 0;
        __syncthreads();
        sm[threadIdx.x] += t;
        __syncthreads();
    }
    if (i < n) g_rowoff[i] = sm[threadIdx.x] - v;
    if (threadIdx.x == 1023) g_bsum[blockIdx.x] = sm[1023];
}

__global__ void k_scan2(int nb) {
    if (threadIdx.x == 0 && blockIdx.x == 0) {
        int s = 0;
        for (int b = 0; b < nb; b++) { int t = g_bsum[b]; g_bsum[b] = s; s += t; }
    }
}

__global__ void k_scan3(int n, int e) {
    int i = blockIdx.x * 1024 + threadIdx.x;
    if (i < n) {
        int r = g_rowoff[i] + g_bsum[i >> 10];
        g_rowoff[i] = r;
        g_cursor[i] = r;
    }
    if (i == 0) g_rowoff[n] = e;
}

__global__ void k_scatter(const int* __restrict__ dst, int e) {
    int i = blockIdx.x * blockDim.x + threadIdx.x;
    if (i < e) {
        int p = atomicAdd(&g_cursor[dst[i]], 1);
        g_eids[p] = i;
    }
}

__device__ __forceinline__ float pick4(float a0, float a1, float a2, float a3, int i) {
    float x = (i & 1) ? a1 : a0;
    float y = (i & 1) ? a3 : a2;
    return (i & 2) ? y : x;
}
__device__ __forceinline__ float pick8(const float v0, const float v1, const float v2,
                                       const float v3, const float v4, const float v5,
                                       const float v6, const float v7, int i) {
    float a = pick4(v0, v1, v2, v3, i & 3);
    float b = pick4(v4, v5, v6, v7, i & 3);
    return (i & 4) ? b : a;
}

// ---- fused online-softmax + aggregate: warp/node, fp16 gather (R8 version) ---
__global__ __launch_bounds__(256)
void k_agg(const int* __restrict__ src, float* __restrict__ out_h,
           float* __restrict__ out_attn, int n) {
    __shared__ float s_w[8][32][8];
    const unsigned FULL = 0xffffffffu;
    const int wid  = threadIdx.x >> 5;
    const int lane = threadIdx.x & 31;
    const int node = blockIdx.x * 8 + wid;
    if (node >= n) return;
    const int h0 = lane >> 2;
    const int beg = g_rowoff[node], end = g_rowoff[node + 1];

    float4 er0 = *(const float4*)(g_er + (size_t)node * 8);
    float4 er1 = *(const float4*)(g_er + (size_t)node * 8 + 4);
    const float er[8] = {er0.x, er0.y, er0.z, er0.w, er1.x, er1.y, er1.z, er1.w};

    float m[8], s_[8], acc[8];
#pragma unroll
    for (int h = 0; h < 8; h++) { m[h] = -1e30f; s_[h] = 0.f; acc[h] = 0.f; }

    for (int base = beg; base < end; base += 32) {
        const int p = base + lane;
        const bool valid = p < end;
        int sr = 0;
        if (valid) sr = src[g_eids[p]];

        float v[8];
        if (valid) {
            float4 l0 = *(const float4*)(g_el + (size_t)sr * 8);
            float4 l1 = *(const float4*)(g_el + (size_t)sr * 8 + 4);
            float lv[8] = {l0.x, l0.y, l0.z, l0.w, l1.x, l1.y, l1.z, l1.w};
#pragma unroll
            for (int h = 0; h < 8; h++) {
                float t = lv[h] + er[h];
                v[h] = t > 0.f ? t : 0.2f * t;
            }
        } else {
#pragma unroll
            for (int h = 0; h < 8; h++) v[h] = -1e30f;
        }

        float bm[8];
#pragma unroll
        for (int h = 0; h < 8; h++) bm[h] = v[h];
#pragma unroll
        for (int off = 16; off; off >>= 1)
#pragma unroll
            for (int h = 0; h < 8; h++)
                bm[h] = fmaxf(bm[h], __shfl_xor_sync(FULL, bm[h], off));

        float sc[8];
#pragma unroll
        for (int h = 0; h < 8; h++) {
            float nm = fmaxf(m[h], bm[h]);
            sc[h] = __expf(m[h] - nm);
            s_[h] *= sc[h];
            m[h] = nm;
        }
        float scH = pick8(sc[0], sc[1], sc[2], sc[3], sc[4], sc[5], sc[6], sc[7], h0);
#pragma unroll
        for (int i = 0; i < 8; i++) acc[i] *= scH;

        float w[8];
#pragma unroll
        for (int h = 0; h < 8; h++) {
            w[h] = valid ? __expf(v[h] - m[h]) : 0.f;
            s_[h] += w[h];
        }
        *(float4*)&s_w[wid][lane][0] = make_float4(w[0], w[1], w[2], w[3]);
        *(float4*)&s_w[wid][lane][4] = make_float4(w[4], w[5], w[6], w[7]);
        __syncwarp();

        const int cnt = min(32, end - base);
        int j = 0;
        for (; j + 4 <= cnt; j += 4) {
            int s0 = __shfl_sync(FULL, sr, j);
            int s1 = __shfl_sync(FULL, sr, j + 1);
            int s2 = __shfl_sync(FULL, sr, j + 2);
            int s3 = __shfl_sync(FULL, sr, j + 3);
            uint4 u0 = ((const uint4*)(g_fth + (size_t)s0 * HD))[lane];
            uint4 u1 = ((const uint4*)(g_fth + (size_t)s1 * HD))[lane];
            uint4 u2 = ((const uint4*)(g_fth + (size_t)s2 * HD))[lane];
            uint4 u3 = ((const uint4*)(g_fth + (size_t)s3 * HD))[lane];
            float w0 = s_w[wid][j][h0], w1 = s_w[wid][j + 1][h0];
            float w2 = s_w[wid][j + 2][h0], w3 = s_w[wid][j + 3][h0];
#pragma unroll
            for (int t = 0; t < 4; t++) {
                float2 f0 = __half22float2(((const __half2*)&u0)[t]);
                float2 f1 = __half22float2(((const __half2*)&u1)[t]);
                float2 f2 = __half22float2(((const __half2*)&u2)[t]);
                float2 f3 = __half22float2(((const __half2*)&u3)[t]);
                acc[2 * t]     += w0 * f0.x + w1 * f1.x + w2 * f2.x + w3 * f3.x;
                acc[2 * t + 1] += w0 * f0.y + w1 * f1.y + w2 * f2.y + w3 * f3.y;
            }
        }
        for (; j < cnt; j++) {
            int s0 = __shfl_sync(FULL, sr, j);
            uint4 u0 = ((const uint4*)(g_fth + (size_t)s0 * HD))[lane];
            float w0 = s_w[wid][j][h0];
#pragma unroll
            for (int t = 0; t < 4; t++) {
                float2 f0 = __half22float2(((const __half2*)&u0)[t]);
                acc[2 * t]     += w0 * f0.x;
                acc[2 * t + 1] += w0 * f0.y;
            }
        }
        __syncwarp();
    }

#pragma unroll
    for (int off = 16; off; off >>= 1)
#pragma unroll
        for (int h = 0; h < 8; h++)
            s_[h] += __shfl_xor_sync(FULL, s_[h], off);
    float inv[8];
#pragma unroll
    for (int h = 0; h < 8; h++) inv[h] = (s_[h] > 0.f) ? 1.f / s_[h] : 0.f;

    for (int p = beg + lane; p < end; p += 32) {
        int e = g_eids[p];
        int s = src[e];
        float4 l0 = *(const float4*)(g_el + (size_t)s * 8);
        float4 l1 = *(const float4*)(g_el + (size_t)s * 8 + 4);
        float lv[8] = {l0.x, l0.y, l0.z, l0.w, l1.x, l1.y, l1.z, l1.w};
        float a[8];
#pragma unroll
        for (int h = 0; h < 8; h++) {
            float t = lv[h] + er[h];
            t = t > 0.f ? t : 0.2f * t;
            a[h] = __expf(t - m[h]) * inv[h];
        }
        *(float4*)(out_attn + (size_t)e * 8)     = make_float4(a[0], a[1], a[2], a[3]);
        *(float4*)(out_attn + (size_t)e * 8 + 4) = make_float4(a[4], a[5], a[6], a[7]);
    }

    float invH = pick8(inv[0], inv[1], inv[2], inv[3], inv[4], inv[5], inv[6], inv[7], h0);
#pragma unroll
    for (int i = 0; i < 8; i++) acc[i] *= invH;
#pragma unroll
    for (int off = 4; off <= 16; off <<= 1)
#pragma unroll
        for (int i = 0; i < 8; i++)
            acc[i] += __shfl_xor_sync(FULL, acc[i], off);

    if (lane < 4) {
        float4 b0 = ((const float4*)g_bmean)[lane * 2];
        float4 b1 = ((const float4*)g_bmean)[lane * 2 + 1];
        float4* o = (float4*)(out_h + (size_t)node * 32 + lane * 8);
        o[0] = make_float4(acc[0] * 0.125f + b0.x, acc[1] * 0.125f + b0.y,
                           acc[2] * 0.125f + b0.z, acc[3] * 0.125f + b0.w);
        o[1] = make_float4(acc[4] * 0.125f + b1.x, acc[5] * 0.125f + b1.y,
                           acc[6] * 0.125f + b1.z, acc[7] * 0.125f + b1.w);
    }
}

// ---------------- launch --------------------------------------------------------
extern "C" void kernel_launch(void* const* d_in, const int* in_sizes, int n_in,
                              void* d_out, int out_size) {
    const float* feat = (const float*)d_in[0];
    const int*   src  = (const int*)d_in[1];
    const int*   dst  = (const int*)d_in[2];
    const float* W    = (const float*)d_in[3];
    const float* al   = (const float*)d_in[4];
    const float* ar   = (const float*)d_in[5];
    const float* bias = (const float*)d_in[6];

    int n = in_sizes[0] / INF_;
    int e = in_sizes[1];

    float* out      = (float*)d_out;
    float* out_h    = out;
    float* out_attn = out + (size_t)n * 32;

    const int SMEM = (128 * 132 + 256 * 132) * 4;   // 202,752 B
    cudaFuncSetAttribute(k_gemm, cudaFuncAttributeMaxDynamicSharedMemorySize, SMEM);

    int nb = (n + 1023) / 1024;

    k_init<<<(n + 255) / 256, 256>>>(n);                          // 0
    k_hist<<<(e + 255) / 256, 256>>>(dst, e);                     // 1
    k_scan1<<<nb, 1024>>>(n);                                     // 2
    k_gemm<<<(n + 127) / 128, 512, SMEM>>>(feat, W, al, ar, n);   // 3 <- profiled
    k_scan2<<<1, 32>>>(nb);                                       // 4
    k_scan3<<<nb, 1024>>>(n, e);                                  // 5
    k_scatter<<<(e + 255) / 256, 256>>>(dst, e);                  // 6
    k_bias<<<1, 32>>>(bias);                                      // 7
    k_agg<<<(n + 7) / 8, 256>>>(src, out_h, out_attn, n);         // 8
}

// round 11
// speedup vs baseline: 1.2465x; 1.0365x over previous
#include <cuda_runtime.h>
#include <cuda_fp16.h>

#define MAXN 100000
#define MAXE 1600000
#define HD   256
#define INF_ 128

// ---------------- scratch ----------------------------------------------------
__device__ __half g_fth[(size_t)MAXN * HD];   // 51.2 MB (L2-resident)
__device__ float  g_el[MAXN * 8];
__device__ float  g_er[MAXN * 8];
__device__ float  g_bmean[32];
__device__ int    g_deg[MAXN];
__device__ int    g_rowoff[MAXN + 1];
__device__ int    g_cursor[MAXN];
__device__ int    g_eids[MAXE];
__device__ int    g_bsum[1024];

// ---------------- init --------------------------------------------------------
__global__ void k_init(int n) {
    int i = blockIdx.x * blockDim.x + threadIdx.x;
    if (i < n) g_deg[i] = 0;
}

__global__ void k_bias(const float* __restrict__ bias) {
    int c = threadIdx.x;
    float s = 0.f;
#pragma unroll
    for (int h = 0; h < 8; h++) s += bias[h * 32 + c];
    g_bmean[c] = s * 0.125f;
}

// ---------------- FP16 tensor-core GEMM + fused el/er + fp16 ft ---------------
// block 512 = 16 warps, tile M=128 N=256 K=128, warp grid 4(M)x4(N), warp 32x64.
// mma.m16n8k16.f16 (f32 accum). A smem [128][136] halves row-major;
// W smem TRANSPOSED [n=256][k=136] halves. Fragment LDS conflict-free
// (bank = 4*lr + lc, unique per lane).
__global__ __launch_bounds__(512, 1)
void k_gemm(const float* __restrict__ feat, const float* __restrict__ W,
            const float* __restrict__ al, const float* __restrict__ ar, int n) {
    extern __shared__ __half smh[];
    __half* As = smh;                       // 128 x 136 halves (34.8 KB)
    __half* Bs = As + 128 * 136;            // 256 x 136 halves (69.6 KB)
    const int tid = threadIdx.x;
    const int n0  = blockIdx.x * 128;

    // fill A (feat tile), fp16-converted, zero-padded rows
    for (int i = tid; i < 4096; i += 512) {
        int r = i >> 5, c4 = i & 31;
        float4 v = make_float4(0.f, 0.f, 0.f, 0.f);
        if (n0 + r < n) v = ((const float4*)feat)[(size_t)(n0 + r) * 32 + c4];
        __half2 h01 = __floats2half2_rn(v.x, v.y);
        __half2 h23 = __floats2half2_rn(v.z, v.w);
        uint2 u;
        u.x = *(unsigned int*)&h01;
        u.y = *(unsigned int*)&h23;
        *(uint2*)(As + r * 136 + 4 * c4) = u;
    }
    // fill W^T, fp16-converted
    for (int i = tid; i < 8192; i += 512) {
        int k = i >> 6, n4 = i & 63;
        float4 v = ((const float4*)W)[(size_t)k * 64 + n4];
        Bs[(4 * n4 + 0) * 136 + k] = __float2half_rn(v.x);
        Bs[(4 * n4 + 1) * 136 + k] = __float2half_rn(v.y);
        Bs[(4 * n4 + 2) * 136 + k] = __float2half_rn(v.z);
        Bs[(4 * n4 + 3) * 136 + k] = __float2half_rn(v.w);
    }
    __syncthreads();

    const unsigned FULL = 0xffffffffu;
    const int w    = tid >> 5;
    const int lane = tid & 31;
    const int mw   = w >> 2;          // M warp (0..3) -> rows mw*32..+31
    const int nw   = w & 3;           // N warp (0..3) -> cols nw*64..+63
    const int lr   = lane >> 2;       // groupID 0..7
    const int lc   = lane & 3;        // tid-in-group 0..3

    float acc[2][8][4];
#pragma unroll
    for (int mt = 0; mt < 2; mt++)
#pragma unroll
        for (int nt = 0; nt < 8; nt++)
#pragma unroll
            for (int q = 0; q < 4; q++) acc[mt][nt][q] = 0.f;

#pragma unroll
    for (int kc = 0; kc < 8; kc++) {
        const int kb = kc * 16;
        unsigned int a[2][4];
#pragma unroll
        for (int mt = 0; mt < 2; mt++) {
            const __half* ap = As + (mw * 32 + mt * 16 + lr) * 136 + kb + 2 * lc;
            a[mt][0] = *(const unsigned int*)(ap);
            a[mt][1] = *(const unsigned int*)(ap + 8 * 136);
            a[mt][2] = *(const unsigned int*)(ap + 8);
            a[mt][3] = *(const unsigned int*)(ap + 8 * 136 + 8);
        }
        unsigned int b[8][2];
#pragma unroll
        for (int nt = 0; nt < 8; nt++) {
            const __half* bp = Bs + (nw * 64 + nt * 8 + lr) * 136 + kb + 2 * lc;
            b[nt][0] = *(const unsigned int*)(bp);
            b[nt][1] = *(const unsigned int*)(bp + 8);
        }
#pragma unroll
        for (int mt = 0; mt < 2; mt++)
#pragma unroll
            for (int nt = 0; nt < 8; nt++)
                asm volatile(
                    "mma.sync.aligned.m16n8k16.row.col.f32.f16.f16.f32 "
                    "{%0,%1,%2,%3}, {%4,%5,%6,%7}, {%8,%9}, {%0,%1,%2,%3};"
                    : "+f"(acc[mt][nt][0]), "+f"(acc[mt][nt][1]),
                      "+f"(acc[mt][nt][2]), "+f"(acc[mt][nt][3])
                    : "r"(a[mt][0]), "r"(a[mt][1]), "r"(a[mt][2]), "r"(a[mt][3]),
                      "r"(b[nt][0]), "r"(b[nt][1]));
    }

    // ---- epilogue: fp16 ft store + fused el/er (heads local to warp) ----
#pragma unroll
    for (int mt = 0; mt < 2; mt++) {
#pragma unroll
        for (int rh = 0; rh < 2; rh++) {
            int row  = mw * 32 + mt * 16 + rh * 8 + lr;
            int node = n0 + row;
            bool ok  = node < n;
            if (ok) {
                __half* fo = g_fth + (size_t)node * HD + nw * 64 + 2 * lc;
#pragma unroll
                for (int nt = 0; nt < 8; nt++) {
                    __half2 hv = __floats2half2_rn(acc[mt][nt][rh * 2],
                                                   acc[mt][nt][rh * 2 + 1]);
                    *(__half2*)(fo + nt * 8) = hv;
                }
            }
#pragma unroll
            for (int hh = 0; hh < 2; hh++) {
                int head = 2 * nw + hh;
                float pl = 0.f, pr = 0.f;
#pragma unroll
                for (int nt4 = 0; nt4 < 4; nt4++) {
                    int nt  = hh * 4 + nt4;
                    int cih = 8 * nt4 + 2 * lc;
                    float v0 = acc[mt][nt][rh * 2], v1 = acc[mt][nt][rh * 2 + 1];
                    pl += v0 * __ldg(al + head * 32 + cih) + v1 * __ldg(al + head * 32 + cih + 1);
                    pr += v0 * __ldg(ar + head * 32 + cih) + v1 * __ldg(ar + head * 32 + cih + 1);
                }
                pl += __shfl_xor_sync(FULL, pl, 1);
                pl += __shfl_xor_sync(FULL, pl, 2);
                pr += __shfl_xor_sync(FULL, pr, 1);
                pr += __shfl_xor_sync(FULL, pr, 2);
                if (lc == 0 && ok) {
                    g_el[node * 8 + head] = pl;
                    g_er[node * 8 + head] = pr;
                }
            }
        }
    }
}

// ---------------- CSR build ----------------------------------------------------
__global__ void k_hist(const int* __restrict__ dst, int e) {
    int i = blockIdx.x * blockDim.x + threadIdx.x;
    if (i < e) atomicAdd(&g_deg[dst[i]], 1);
}

__global__ void k_scan1(int n) {
    __shared__ int sm[1024];
    int i = blockIdx.x * 1024 + threadIdx.x;
    int v = (i < n) ? g_deg[i] : 0;
    sm[threadIdx.x] = v;
    __syncthreads();
    for (int off = 1; off < 1024; off <<= 1) {
        int t = (threadIdx.x >= off) ? sm[threadIdx.x - off] : 0;
        __syncthreads();
        sm[threadIdx.x] += t;
        __syncthreads();
    }
    if (i < n) g_rowoff[i] = sm[threadIdx.x] - v;
    if (threadIdx.x == 1023) g_bsum[blockIdx.x] = sm[1023];
}

__global__ void k_scan2(int nb) {
    if (threadIdx.x == 0 && blockIdx.x == 0) {
        int s = 0;
        for (int b = 0; b < nb; b++) { int t = g_bsum[b]; g_bsum[b] = s; s += t; }
    }
}

__global__ void k_scan3(int n, int e) {
    int i = blockIdx.x * 1024 + threadIdx.x;
    if (i < n) {
        int r = g_rowoff[i] + g_bsum[i >> 10];
        g_rowoff[i] = r;
        g_cursor[i] = r;
    }
    if (i == 0) g_rowoff[n] = e;
}

__global__ void k_scatter(const int* __restrict__ dst, int e) {
    int i = blockIdx.x * blockDim.x + threadIdx.x;
    if (i < e) {
        int p = atomicAdd(&g_cursor[dst[i]], 1);
        g_eids[p] = i;
    }
}

__device__ __forceinline__ float pick4(float a0, float a1, float a2, float a3, int i) {
    float x = (i & 1) ? a1 : a0;
    float y = (i & 1) ? a3 : a2;
    return (i & 2) ? y : x;
}
__device__ __forceinline__ float pick8(const float v0, const float v1, const float v2,
                                       const float v3, const float v4, const float v5,
                                       const float v6, const float v7, int i) {
    float a = pick4(v0, v1, v2, v3, i & 3);
    float b = pick4(v4, v5, v6, v7, i & 3);
    return (i & 4) ? b : a;
}

// ---- fused online-softmax + aggregate: warp/node, fp16 gather (R8 version) ---
__global__ __launch_bounds__(256)
void k_agg(const int* __restrict__ src, float* __restrict__ out_h,
           float* __restrict__ out_attn, int n) {
    __shared__ float s_w[8][32][8];
    const unsigned FULL = 0xffffffffu;
    const int wid  = threadIdx.x >> 5;
    const int lane = threadIdx.x & 31;
    const int node = blockIdx.x * 8 + wid;
    if (node >= n) return;
    const int h0 = lane >> 2;
    const int beg = g_rowoff[node], end = g_rowoff[node + 1];

    float4 er0 = *(const float4*)(g_er + (size_t)node * 8);
    float4 er1 = *(const float4*)(g_er + (size_t)node * 8 + 4);
    const float er[8] = {er0.x, er0.y, er0.z, er0.w, er1.x, er1.y, er1.z, er1.w};

    float m[8], s_[8], acc[8];
#pragma unroll
    for (int h = 0; h < 8; h++) { m[h] = -1e30f; s_[h] = 0.f; acc[h] = 0.f; }

    for (int base = beg; base < end; base += 32) {
        const int p = base + lane;
        const bool valid = p < end;
        int sr = 0;
        if (valid) sr = src[g_eids[p]];

        float v[8];
        if (valid) {
            float4 l0 = *(const float4*)(g_el + (size_t)sr * 8);
            float4 l1 = *(const float4*)(g_el + (size_t)sr * 8 + 4);
            float lv[8] = {l0.x, l0.y, l0.z, l0.w, l1.x, l1.y, l1.z, l1.w};
#pragma unroll
            for (int h = 0; h < 8; h++) {
                float t = lv[h] + er[h];
                v[h] = t > 0.f ? t : 0.2f * t;
            }
        } else {
#pragma unroll
            for (int h = 0; h < 8; h++) v[h] = -1e30f;
        }

        float bm[8];
#pragma unroll
        for (int h = 0; h < 8; h++) bm[h] = v[h];
#pragma unroll
        for (int off = 16; off; off >>= 1)
#pragma unroll
            for (int h = 0; h < 8; h++)
                bm[h] = fmaxf(bm[h], __shfl_xor_sync(FULL, bm[h], off));

        float sc[8];
#pragma unroll
        for (int h = 0; h < 8; h++) {
            float nm = fmaxf(m[h], bm[h]);
            sc[h] = __expf(m[h] - nm);
            s_[h] *= sc[h];
            m[h] = nm;
        }
        float scH = pick8(sc[0], sc[1], sc[2], sc[3], sc[4], sc[5], sc[6], sc[7], h0);
#pragma unroll
        for (int i = 0; i < 8; i++) acc[i] *= scH;

        float w[8];
#pragma unroll
        for (int h = 0; h < 8; h++) {
            w[h] = valid ? __expf(v[h] - m[h]) : 0.f;
            s_[h] += w[h];
        }
        *(float4*)&s_w[wid][lane][0] = make_float4(w[0], w[1], w[2], w[3]);
        *(float4*)&s_w[wid][lane][4] = make_float4(w[4], w[5], w[6], w[7]);
        __syncwarp();

        const int cnt = min(32, end - base);
        int j = 0;
        for (; j + 4 <= cnt; j += 4) {
            int s0 = __shfl_sync(FULL, sr, j);
            int s1 = __shfl_sync(FULL, sr, j + 1);
            int s2 = __shfl_sync(FULL, sr, j + 2);
            int s3 = __shfl_sync(FULL, sr, j + 3);
            uint4 u0 = ((const uint4*)(g_fth + (size_t)s0 * HD))[lane];
            uint4 u1 = ((const uint4*)(g_fth + (size_t)s1 * HD))[lane];
            uint4 u2 = ((const uint4*)(g_fth + (size_t)s2 * HD))[lane];
            uint4 u3 = ((const uint4*)(g_fth + (size_t)s3 * HD))[lane];
            float w0 = s_w[wid][j][h0], w1 = s_w[wid][j + 1][h0];
            float w2 = s_w[wid][j + 2][h0], w3 = s_w[wid][j + 3][h0];
#pragma unroll
            for (int t = 0; t < 4; t++) {
                float2 f0 = __half22float2(((const __half2*)&u0)[t]);
                float2 f1 = __half22float2(((const __half2*)&u1)[t]);
                float2 f2 = __half22float2(((const __half2*)&u2)[t]);
                float2 f3 = __half22float2(((const __half2*)&u3)[t]);
                acc[2 * t]     += w0 * f0.x + w1 * f1.x + w2 * f2.x + w3 * f3.x;
                acc[2 * t + 1] += w0 * f0.y + w1 * f1.y + w2 * f2.y + w3 * f3.y;
            }
        }
        for (; j < cnt; j++) {
            int s0 = __shfl_sync(FULL, sr, j);
            uint4 u0 = ((const uint4*)(g_fth + (size_t)s0 * HD))[lane];
            float w0 = s_w[wid][j][h0];
#pragma unroll
            for (int t = 0; t < 4; t++) {
                float2 f0 = __half22float2(((const __half2*)&u0)[t]);
                acc[2 * t]     += w0 * f0.x;
                acc[2 * t + 1] += w0 * f0.y;
            }
        }
        __syncwarp();
    }

#pragma unroll
    for (int off = 16; off; off >>= 1)
#pragma unroll
        for (int h = 0; h < 8; h++)
            s_[h] += __shfl_xor_sync(FULL, s_[h], off);
    float inv[8];
#pragma unroll
    for (int h = 0; h < 8; h++) inv[h] = (s_[h] > 0.f) ? 1.f / s_[h] : 0.f;

    for (int p = beg + lane; p < end; p += 32) {
        int e = g_eids[p];
        int s = src[e];
        float4 l0 = *(const float4*)(g_el + (size_t)s * 8);
        float4 l1 = *(const float4*)(g_el + (size_t)s * 8 + 4);
        float lv[8] = {l0.x, l0.y, l0.z, l0.w, l1.x, l1.y, l1.z, l1.w};
        float a[8];
#pragma unroll
        for (int h = 0; h < 8; h++) {
            float t = lv[h] + er[h];
            t = t > 0.f ? t : 0.2f * t;
            a[h] = __expf(t - m[h]) * inv[h];
        }
        *(float4*)(out_attn + (size_t)e * 8)     = make_float4(a[0], a[1], a[2], a[3]);
        *(float4*)(out_attn + (size_t)e * 8 + 4) = make_float4(a[4], a[5], a[6], a[7]);
    }

    float invH = pick8(inv[0], inv[1], inv[2], inv[3], inv[4], inv[5], inv[6], inv[7], h0);
#pragma unroll
    for (int i = 0; i < 8; i++) acc[i] *= invH;
#pragma unroll
    for (int off = 4; off <= 16; off <<= 1)
#pragma unroll
        for (int i = 0; i < 8; i++)
            acc[i] += __shfl_xor_sync(FULL, acc[i], off);

    if (lane < 4) {
        float4 b0 = ((const float4*)g_bmean)[lane * 2];
        float4 b1 = ((const float4*)g_bmean)[lane * 2 + 1];
        float4* o = (float4*)(out_h + (size_t)node * 32 + lane * 8);
        o[0] = make_float4(acc[0] * 0.125f + b0.x, acc[1] * 0.125f + b0.y,
                           acc[2] * 0.125f + b0.z, acc[3] * 0.125f + b0.w);
        o[1] = make_float4(acc[4] * 0.125f + b1.x, acc[5] * 0.125f + b1.y,
                           acc[6] * 0.125f + b1.z, acc[7] * 0.125f + b1.w);
    }
}

// ---------------- launch --------------------------------------------------------
extern "C" void kernel_launch(void* const* d_in, const int* in_sizes, int n_in,
                              void* d_out, int out_size) {
    const float* feat = (const float*)d_in[0];
    const int*   src  = (const int*)d_in[1];
    const int*   dst  = (const int*)d_in[2];
    const float* W    = (const float*)d_in[3];
    const float* al   = (const float*)d_in[4];
    const float* ar   = (const float*)d_in[5];
    const float* bias = (const float*)d_in[6];

    int n = in_sizes[0] / INF_;
    int e = in_sizes[1];

    float* out      = (float*)d_out;
    float* out_h    = out;
    float* out_attn = out + (size_t)n * 32;

    const int SMEM = (128 * 136 + 256 * 136) * 2;   // 104,448 B
    cudaFuncSetAttribute(k_gemm, cudaFuncAttributeMaxDynamicSharedMemorySize, SMEM);

    int nb = (n + 1023) / 1024;

    k_init<<<(n + 255) / 256, 256>>>(n);                          // 0
    k_hist<<<(e + 255) / 256, 256>>>(dst, e);                     // 1
    k_scan1<<<nb, 1024>>>(n);                                     // 2
    k_gemm<<<(n + 127) / 128, 512, SMEM>>>(feat, W, al, ar, n);   // 3 <- profiled
    k_scan2<<<1, 32>>>(nb);                                       // 4
    k_scan3<<<nb, 1024>>>(n, e);                                  // 5
    k_scatter<<<(e + 255) / 256, 256>>>(dst, e);                  // 6
    k_bias<<<1, 32>>>(bias);                                      // 7
    k_agg<<<(n + 7) / 8, 256>>>(src, out_h, out_attn, n);         // 8
}

// round 12
// speedup vs baseline: 1.2888x; 1.0339x over previous
#include <cuda_runtime.h>
#include <cuda_fp16.h>

#define MAXN 100000
#define MAXE 1600000
#define HD   256
#define INF_ 128

// ---------------- scratch ----------------------------------------------------
__device__ __half g_fth[(size_t)MAXN * HD];   // 51.2 MB (L2-resident)
__device__ float  g_el[MAXN * 8];
__device__ float  g_er[MAXN * 8];
__device__ float  g_bmean[32];
__device__ int    g_deg[MAXN];
__device__ int    g_rowoff[MAXN + 1];
__device__ int    g_cursor[MAXN];
__device__ int    g_eids[MAXE];
__device__ int    g_bsum[1024];

// ---------------- init --------------------------------------------------------
__global__ void k_init(int n) {
    int i = blockIdx.x * blockDim.x + threadIdx.x;
    if (i < n) g_deg[i] = 0;
}

__global__ void k_bias(const float* __restrict__ bias) {
    int c = threadIdx.x;
    float s = 0.f;
#pragma unroll
    for (int h = 0; h < 8; h++) s += bias[h * 32 + c];
    g_bmean[c] = s * 0.125f;
}

// ---------------- FP16 tensor-core GEMM + fused el/er + fp16 ft ---------------
__global__ __launch_bounds__(512, 1)
void k_gemm(const float* __restrict__ feat, const float* __restrict__ W,
            const float* __restrict__ al, const float* __restrict__ ar, int n) {
    extern __shared__ __half smh[];
    __half* As = smh;                       // 128 x 136 halves
    __half* Bs = As + 128 * 136;            // 256 x 136 halves (W^T)
    const int tid = threadIdx.x;
    const int n0  = blockIdx.x * 128;

    for (int i = tid; i < 4096; i += 512) {
        int r = i >> 5, c4 = i & 31;
        float4 v = make_float4(0.f, 0.f, 0.f, 0.f);
        if (n0 + r < n) v = ((const float4*)feat)[(size_t)(n0 + r) * 32 + c4];
        __half2 h01 = __floats2half2_rn(v.x, v.y);
        __half2 h23 = __floats2half2_rn(v.z, v.w);
        uint2 u;
        u.x = *(unsigned int*)&h01;
        u.y = *(unsigned int*)&h23;
        *(uint2*)(As + r * 136 + 4 * c4) = u;
    }
    for (int i = tid; i < 8192; i += 512) {
        int k = i >> 6, n4 = i & 63;
        float4 v = ((const float4*)W)[(size_t)k * 64 + n4];
        Bs[(4 * n4 + 0) * 136 + k] = __float2half_rn(v.x);
        Bs[(4 * n4 + 1) * 136 + k] = __float2half_rn(v.y);
        Bs[(4 * n4 + 2) * 136 + k] = __float2half_rn(v.z);
        Bs[(4 * n4 + 3) * 136 + k] = __float2half_rn(v.w);
    }
    __syncthreads();

    const unsigned FULL = 0xffffffffu;
    const int w    = tid >> 5;
    const int lane = tid & 31;
    const int mw   = w >> 2;
    const int nw   = w & 3;
    const int lr   = lane >> 2;
    const int lc   = lane & 3;

    float acc[2][8][4];
#pragma unroll
    for (int mt = 0; mt < 2; mt++)
#pragma unroll
        for (int nt = 0; nt < 8; nt++)
#pragma unroll
            for (int q = 0; q < 4; q++) acc[mt][nt][q] = 0.f;

#pragma unroll
    for (int kc = 0; kc < 8; kc++) {
        const int kb = kc * 16;
        unsigned int a[2][4];
#pragma unroll
        for (int mt = 0; mt < 2; mt++) {
            const __half* ap = As + (mw * 32 + mt * 16 + lr) * 136 + kb + 2 * lc;
            a[mt][0] = *(const unsigned int*)(ap);
            a[mt][1] = *(const unsigned int*)(ap + 8 * 136);
            a[mt][2] = *(const unsigned int*)(ap + 8);
            a[mt][3] = *(const unsigned int*)(ap + 8 * 136 + 8);
        }
        unsigned int b[8][2];
#pragma unroll
        for (int nt = 0; nt < 8; nt++) {
            const __half* bp = Bs + (nw * 64 + nt * 8 + lr) * 136 + kb + 2 * lc;
            b[nt][0] = *(const unsigned int*)(bp);
            b[nt][1] = *(const unsigned int*)(bp + 8);
        }
#pragma unroll
        for (int mt = 0; mt < 2; mt++)
#pragma unroll
            for (int nt = 0; nt < 8; nt++)
                asm volatile(
                    "mma.sync.aligned.m16n8k16.row.col.f32.f16.f16.f32 "
                    "{%0,%1,%2,%3}, {%4,%5,%6,%7}, {%8,%9}, {%0,%1,%2,%3};"
                    : "+f"(acc[mt][nt][0]), "+f"(acc[mt][nt][1]),
                      "+f"(acc[mt][nt][2]), "+f"(acc[mt][nt][3])
                    : "r"(a[mt][0]), "r"(a[mt][1]), "r"(a[mt][2]), "r"(a[mt][3]),
                      "r"(b[nt][0]), "r"(b[nt][1]));
    }

#pragma unroll
    for (int mt = 0; mt < 2; mt++) {
#pragma unroll
        for (int rh = 0; rh < 2; rh++) {
            int row  = mw * 32 + mt * 16 + rh * 8 + lr;
            int node = n0 + row;
            bool ok  = node < n;
            if (ok) {
                __half* fo = g_fth + (size_t)node * HD + nw * 64 + 2 * lc;
#pragma unroll
                for (int nt = 0; nt < 8; nt++) {
                    __half2 hv = __floats2half2_rn(acc[mt][nt][rh * 2],
                                                   acc[mt][nt][rh * 2 + 1]);
                    *(__half2*)(fo + nt * 8) = hv;
                }
            }
#pragma unroll
            for (int hh = 0; hh < 2; hh++) {
                int head = 2 * nw + hh;
                float pl = 0.f, pr = 0.f;
#pragma unroll
                for (int nt4 = 0; nt4 < 4; nt4++) {
                    int nt  = hh * 4 + nt4;
                    int cih = 8 * nt4 + 2 * lc;
                    float v0 = acc[mt][nt][rh * 2], v1 = acc[mt][nt][rh * 2 + 1];
                    pl += v0 * __ldg(al + head * 32 + cih) + v1 * __ldg(al + head * 32 + cih + 1);
                    pr += v0 * __ldg(ar + head * 32 + cih) + v1 * __ldg(ar + head * 32 + cih + 1);
                }
                pl += __shfl_xor_sync(FULL, pl, 1);
                pl += __shfl_xor_sync(FULL, pl, 2);
                pr += __shfl_xor_sync(FULL, pr, 1);
                pr += __shfl_xor_sync(FULL, pr, 2);
                if (lc == 0 && ok) {
                    g_el[node * 8 + head] = pl;
                    g_er[node * 8 + head] = pr;
                }
            }
        }
    }
}

// ---------------- CSR build ----------------------------------------------------
__global__ void k_hist(const int* __restrict__ dst, int e) {
    int i = blockIdx.x * blockDim.x + threadIdx.x;
    if (i < e) atomicAdd(&g_deg[dst[i]], 1);
}

__global__ void k_scan1(int n) {
    __shared__ int sm[1024];
    int i = blockIdx.x * 1024 + threadIdx.x;
    int v = (i < n) ? g_deg[i] : 0;
    sm[threadIdx.x] = v;
    __syncthreads();
    for (int off = 1; off < 1024; off <<= 1) {
        int t = (threadIdx.x >= off) ? sm[threadIdx.x - off] : 0;
        __syncthreads();
        sm[threadIdx.x] += t;
        __syncthreads();
    }
    if (i < n) g_rowoff[i] = sm[threadIdx.x] - v;
    if (threadIdx.x == 1023) g_bsum[blockIdx.x] = sm[1023];
}

__global__ void k_scan2(int nb) {
    if (threadIdx.x == 0 && blockIdx.x == 0) {
        int s = 0;
        for (int b = 0; b < nb; b++) { int t = g_bsum[b]; g_bsum[b] = s; s += t; }
    }
}

__global__ void k_scan3(int n, int e) {
    int i = blockIdx.x * 1024 + threadIdx.x;
    if (i < n) {
        int r = g_rowoff[i] + g_bsum[i >> 10];
        g_rowoff[i] = r;
        g_cursor[i] = r;
    }
    if (i == 0) g_rowoff[n] = e;
}

__global__ void k_scatter(const int* __restrict__ dst, int e) {
    int i = blockIdx.x * blockDim.x + threadIdx.x;
    if (i < e) {
        int p = atomicAdd(&g_cursor[dst[i]], 1);
        g_eids[p] = i;
    }
}

__device__ __forceinline__ float pick4(float a0, float a1, float a2, float a3, int i) {
    float x = (i & 1) ? a1 : a0;
    float y = (i & 1) ? a3 : a2;
    return (i & 2) ? y : x;
}
__device__ __forceinline__ float pick8(const float v0, const float v1, const float v2,
                                       const float v3, const float v4, const float v5,
                                       const float v6, const float v7, int i) {
    float a = pick4(v0, v1, v2, v3, i & 3);
    float b = pick4(v4, v5, v6, v7, i & 3);
    return (i & 4) ? b : a;
}

// ---- fused online-softmax + aggregate: warp/node, single-batch fast path -----
__global__ __launch_bounds__(256)
void k_agg(const int* __restrict__ src, float* __restrict__ out_h,
           float* __restrict__ out_attn, int n) {
    __shared__ float s_w[8][32][8];
    const unsigned FULL = 0xffffffffu;
    const int wid  = threadIdx.x >> 5;
    const int lane = threadIdx.x & 31;
    const int node = blockIdx.x * 8 + wid;
    if (node >= n) return;
    const int h0 = lane >> 2;
    const int beg = g_rowoff[node], end = g_rowoff[node + 1];

    float4 er0 = *(const float4*)(g_er + (size_t)node * 8);
    float4 er1 = *(const float4*)(g_er + (size_t)node * 8 + 4);
    const float er[8] = {er0.x, er0.y, er0.z, er0.w, er1.x, er1.y, er1.z, er1.w};

    float m[8], s_[8], acc[8];
#pragma unroll
    for (int h = 0; h < 8; h++) { m[h] = -1e30f; s_[h] = 0.f; acc[h] = 0.f; }

    for (int base = beg; base < end; base += 32) {
        const int p = base + lane;
        const bool valid = p < end;
        int sr = 0;
        if (valid) sr = src[g_eids[p]];

        float v[8];
        if (valid) {
            float4 l0 = *(const float4*)(g_el + (size_t)sr * 8);
            float4 l1 = *(const float4*)(g_el + (size_t)sr * 8 + 4);
            float lv[8] = {l0.x, l0.y, l0.z, l0.w, l1.x, l1.y, l1.z, l1.w};
#pragma unroll
            for (int h = 0; h < 8; h++) {
                float t = lv[h] + er[h];
                v[h] = t > 0.f ? t : 0.2f * t;
            }
        } else {
#pragma unroll
            for (int h = 0; h < 8; h++) v[h] = -1e30f;
        }

        float bm[8];
#pragma unroll
        for (int h = 0; h < 8; h++) bm[h] = v[h];
#pragma unroll
        for (int off = 16; off; off >>= 1)
#pragma unroll
            for (int h = 0; h < 8; h++)
                bm[h] = fmaxf(bm[h], __shfl_xor_sync(FULL, bm[h], off));

        if (base == beg) {
            // first batch: accumulators are zero, no rescale needed
#pragma unroll
            for (int h = 0; h < 8; h++) m[h] = bm[h];
        } else {
            float sc[8];
#pragma unroll
            for (int h = 0; h < 8; h++) {
                float nm = fmaxf(m[h], bm[h]);
                sc[h] = __expf(m[h] - nm);
                s_[h] *= sc[h];
                m[h] = nm;
            }
            float scH = pick8(sc[0], sc[1], sc[2], sc[3], sc[4], sc[5], sc[6], sc[7], h0);
#pragma unroll
            for (int i = 0; i < 8; i++) acc[i] *= scH;
        }

        float w[8];
#pragma unroll
        for (int h = 0; h < 8; h++) {
            w[h] = valid ? __expf(v[h] - m[h]) : 0.f;
            s_[h] += w[h];
        }
        *(float4*)&s_w[wid][lane][0] = make_float4(w[0], w[1], w[2], w[3]);
        *(float4*)&s_w[wid][lane][4] = make_float4(w[4], w[5], w[6], w[7]);
        __syncwarp();

        const int cnt = min(32, end - base);
        int j = 0;
        for (; j + 4 <= cnt; j += 4) {
            int s0 = __shfl_sync(FULL, sr, j);
            int s1 = __shfl_sync(FULL, sr, j + 1);
            int s2 = __shfl_sync(FULL, sr, j + 2);
            int s3 = __shfl_sync(FULL, sr, j + 3);
            uint4 u0 = ((const uint4*)(g_fth + (size_t)s0 * HD))[lane];
            uint4 u1 = ((const uint4*)(g_fth + (size_t)s1 * HD))[lane];
            uint4 u2 = ((const uint4*)(g_fth + (size_t)s2 * HD))[lane];
            uint4 u3 = ((const uint4*)(g_fth + (size_t)s3 * HD))[lane];
            float w0 = s_w[wid][j][h0], w1 = s_w[wid][j + 1][h0];
            float w2 = s_w[wid][j + 2][h0], w3 = s_w[wid][j + 3][h0];
#pragma unroll
            for (int t = 0; t < 4; t++) {
                float2 f0 = __half22float2(((const __half2*)&u0)[t]);
                float2 f1 = __half22float2(((const __half2*)&u1)[t]);
                float2 f2 = __half22float2(((const __half2*)&u2)[t]);
                float2 f3 = __half22float2(((const __half2*)&u3)[t]);
                acc[2 * t]     += w0 * f0.x + w1 * f1.x + w2 * f2.x + w3 * f3.x;
                acc[2 * t + 1] += w0 * f0.y + w1 * f1.y + w2 * f2.y + w3 * f3.y;
            }
        }
        for (; j < cnt; j++) {
            int s0 = __shfl_sync(FULL, sr, j);
            uint4 u0 = ((const uint4*)(g_fth + (size_t)s0 * HD))[lane];
            float w0 = s_w[wid][j][h0];
#pragma unroll
            for (int t = 0; t < 4; t++) {
                float2 f0 = __half22float2(((const __half2*)&u0)[t]);
                acc[2 * t]     += w0 * f0.x;
                acc[2 * t + 1] += w0 * f0.y;
            }
        }
        __syncwarp();
    }

#pragma unroll
    for (int off = 16; off; off >>= 1)
#pragma unroll
        for (int h = 0; h < 8; h++)
            s_[h] += __shfl_xor_sync(FULL, s_[h], off);
    float inv[8];
#pragma unroll
    for (int h = 0; h < 8; h++) inv[h] = (s_[h] > 0.f) ? 1.f / s_[h] : 0.f;

    // ---- attn output ----
    if (end - beg <= 32) {
        // FAST PATH (typical: avg degree 16): weights still live in s_w
        int p = beg + lane;
        if (p < end) {
            int e = g_eids[p];
            float4 a0, a1;
            a0.x = s_w[wid][lane][0] * inv[0];
            a0.y = s_w[wid][lane][1] * inv[1];
            a0.z = s_w[wid][lane][2] * inv[2];
            a0.w = s_w[wid][lane][3] * inv[3];
            a1.x = s_w[wid][lane][4] * inv[4];
            a1.y = s_w[wid][lane][5] * inv[5];
            a1.z = s_w[wid][lane][6] * inv[6];
            a1.w = s_w[wid][lane][7] * inv[7];
            *(float4*)(out_attn + (size_t)e * 8)     = a0;
            *(float4*)(out_attn + (size_t)e * 8 + 4) = a1;
        }
    } else {
        // multi-batch: recompute from g_el (rare)
        for (int p = beg + lane; p < end; p += 32) {
            int e = g_eids[p];
            int s = src[e];
            float4 l0 = *(const float4*)(g_el + (size_t)s * 8);
            float4 l1 = *(const float4*)(g_el + (size_t)s * 8 + 4);
            float lv[8] = {l0.x, l0.y, l0.z, l0.w, l1.x, l1.y, l1.z, l1.w};
            float a[8];
#pragma unroll
            for (int h = 0; h < 8; h++) {
                float t = lv[h] + er[h];
                t = t > 0.f ? t : 0.2f * t;
                a[h] = __expf(t - m[h]) * inv[h];
            }
            *(float4*)(out_attn + (size_t)e * 8)     = make_float4(a[0], a[1], a[2], a[3]);
            *(float4*)(out_attn + (size_t)e * 8 + 4) = make_float4(a[4], a[5], a[6], a[7]);
        }
    }

    float invH = pick8(inv[0], inv[1], inv[2], inv[3], inv[4], inv[5], inv[6], inv[7], h0);
#pragma unroll
    for (int i = 0; i < 8; i++) acc[i] *= invH;
#pragma unroll
    for (int off = 4; off <= 16; off <<= 1)
#pragma unroll
        for (int i = 0; i < 8; i++)
            acc[i] += __shfl_xor_sync(FULL, acc[i], off);

    if (lane < 4) {
        float4 b0 = ((const float4*)g_bmean)[lane * 2];
        float4 b1 = ((const float4*)g_bmean)[lane * 2 + 1];
        float4* o = (float4*)(out_h + (size_t)node * 32 + lane * 8);
        o[0] = make_float4(acc[0] * 0.125f + b0.x, acc[1] * 0.125f + b0.y,
                           acc[2] * 0.125f + b0.z, acc[3] * 0.125f + b0.w);
        o[1] = make_float4(acc[4] * 0.125f + b1.x, acc[5] * 0.125f + b1.y,
                           acc[6] * 0.125f + b1.z, acc[7] * 0.125f + b1.w);
    }
}

// ---------------- launch --------------------------------------------------------
extern "C" void kernel_launch(void* const* d_in, const int* in_sizes, int n_in,
                              void* d_out, int out_size) {
    const float* feat = (const float*)d_in[0];
    const int*   src  = (const int*)d_in[1];
    const int*   dst  = (const int*)d_in[2];
    const float* W    = (const float*)d_in[3];
    const float* al   = (const float*)d_in[4];
    const float* ar   = (const float*)d_in[5];
    const float* bias = (const float*)d_in[6];

    int n = in_sizes[0] / INF_;
    int e = in_sizes[1];

    float* out      = (float*)d_out;
    float* out_h    = out;
    float* out_attn = out + (size_t)n * 32;

    const int SMEM = (128 * 136 + 256 * 136) * 2;   // 104,448 B
    cudaFuncSetAttribute(k_gemm, cudaFuncAttributeMaxDynamicSharedMemorySize, SMEM);

    int nb = (n + 1023) / 1024;

    k_init<<<(n + 255) / 256, 256>>>(n);                          // 0
    k_hist<<<(e + 255) / 256, 256>>>(dst, e);                     // 1
    k_scan1<<<nb, 1024>>>(n);                                     // 2
    k_gemm<<<(n + 127) / 128, 512, SMEM>>>(feat, W, al, ar, n);   // 3 <- profiled
    k_scan2<<<1, 32>>>(nb);                                       // 4
    k_scan3<<<nb, 1024>>>(n, e);                                  // 5
    k_scatter<<<(e + 255) / 256, 256>>>(dst, e);                  // 6
    k_bias<<<1, 32>>>(bias);                                      // 7
    k_agg<<<(n + 7) / 8, 256>>>(src, out_h, out_attn, n);         // 8
}